// round 2
// baseline (speedup 1.0000x reference)
#include <cuda_runtime.h>
#include <cstdint>

#define KST  48
#define TLEN 512
#define BDIM 96    // 2 batches x 48 states = 3 full warps

// ---- packed f32x2 helpers (sm_100+) ----
__device__ __forceinline__ unsigned long long fma2(unsigned long long a,
                                                   unsigned long long b,
                                                   unsigned long long c) {
    unsigned long long d;
    asm("fma.rn.f32x2 %0, %1, %2, %3;" : "=l"(d) : "l"(a), "l"(b), "l"(c));
    return d;
}
__device__ __forceinline__ unsigned long long add2(unsigned long long a,
                                                   unsigned long long b) {
    unsigned long long d;
    asm("add.rn.f32x2 %0, %1, %2;" : "=l"(d) : "l"(a), "l"(b));
    return d;
}
__device__ __forceinline__ unsigned long long pack2(float lo, float hi) {
    unsigned long long r;
    asm("mov.b64 %0, {%1, %2};" : "=l"(r) : "f"(lo), "f"(hi));
    return r;
}
__device__ __forceinline__ float2 unpack2(unsigned long long v) {
    float2 f;
    asm("mov.b64 {%0, %1}, %2;" : "=f"(f.x), "=f"(f.y) : "l"(v));
    return f;
}

__global__ __launch_bounds__(BDIM)
void crf_nll_kernel(const float* __restrict__ emis,   // [B, T, K]
                    const int*   __restrict__ lab,    // [B, T]
                    const float* __restrict__ trans,  // [K, K]
                    float*       __restrict__ out)    // [B]
{
    __shared__ __align__(16) float strans[KST * KST];      // raw trans (score + expT build)
    __shared__ __align__(16) float pbuf[2][2][KST];        // ping-pong p = exp(alpha)
    __shared__ __align__(16) float salpha[2][KST];         // alpha exchange for renorm
    __shared__ float sred[BDIM];

    const int tid = threadIdx.x;
    const int sub = tid / KST;            // which batch within the block (0/1)
    const int j   = tid - sub * KST;      // output state owned by this thread
    const int b   = blockIdx.x * 2 + sub;

    // stage transition matrix in shared
    for (int i = tid; i < KST * KST; i += BDIM) strans[i] = trans[i];
    __syncthreads();

    // E column in registers, packed as 24 f32x2: ec2[q] = (exp(T[2q][j]), exp(T[2q+1][j]))
    unsigned long long ec2[KST / 2];
#pragma unroll
    for (int q = 0; q < KST / 2; ++q) {
        float e0 = __expf(strans[(2 * q)     * KST + j]);
        float e1 = __expf(strans[(2 * q + 1) * KST + j]);
        ec2[q] = pack2(e0, e1);
    }

    // ---- sequence score (unary + binary), t-strided across 48 threads per batch ----
    const int*   lb  = lab  + b * TLEN;
    const float* eb0 = emis + (size_t)b * TLEN * KST;
    float part = 0.f;
    for (int t = j; t < TLEN; t += KST) {
        int l0 = lb[t];
        part += eb0[t * KST + l0];
        if (t + 1 < TLEN) part += strans[l0 * KST + lb[t + 1]];
    }
    sred[tid] = part;
    __syncthreads();
    float score = 0.f;
    if (j == 0) {
#pragma unroll 8
        for (int k = 0; k < KST; ++k) score += sred[sub * KST + k];
    }

    // ---- forward recursion ----
    const float* eb = eb0 + j;            // emission stream for state j
    float a    = eb[0];                   // alpha (relative to running base M)
    float M    = 0.f;                     // running log-base
    float ecur = eb[KST];                 // e_{t=1}[j], prefetched

    for (int t = 1; t < TLEN; ++t) {
        const int cur = t & 1;
        // prefetch next step's emission early so the LDG overlaps the dot
        float enext = 0.f;
        if (t + 1 < TLEN) enext = eb[(t + 1) * KST];

        if ((t & 7) == 1) {               // renormalize every 8 steps
            salpha[sub][j] = a;
            __syncthreads();
            const float4* ap = (const float4*)&salpha[sub][0];
            float m = -3.4e38f;
#pragma unroll
            for (int q = 0; q < KST / 4; ++q) {
                float4 v = ap[q];
                m = fmaxf(m, fmaxf(fmaxf(v.x, v.y), fmaxf(v.z, v.w)));
            }
            a -= m;
            M += m;
        }

        pbuf[cur][sub][j] = __expf(a);
        __syncthreads();

        // s_j = sum_i p[i] * E[i][j], packed f32x2, 4 independent accumulator chains
        const ulonglong2* pp = (const ulonglong2*)&pbuf[cur][sub][0];
        unsigned long long a0 = 0ull, a1 = 0ull, a2 = 0ull, a3 = 0ull;
#pragma unroll
        for (int q = 0; q < KST / 4; q += 2) {
            ulonglong2 v0 = pp[q];
            ulonglong2 v1 = pp[q + 1];
            a0 = fma2(v0.x, ec2[2 * q],     a0);
            a1 = fma2(v0.y, ec2[2 * q + 1], a1);
            a2 = fma2(v1.x, ec2[2 * q + 2], a2);
            a3 = fma2(v1.y, ec2[2 * q + 3], a3);
        }
        a0 = add2(a0, a2);
        a1 = add2(a1, a3);
        a0 = add2(a0, a1);
        float2 f = unpack2(a0);
        float s  = f.x + f.y;

        a    = __logf(s) + ecur;
        ecur = enext;
    }

    // ---- final logsumexp + output ----
    salpha[sub][j] = a;
    __syncthreads();
    if (j == 0) {
        float m = -3.4e38f;
#pragma unroll 8
        for (int k = 0; k < KST; ++k) m = fmaxf(m, salpha[sub][k]);
        float s = 0.f;
#pragma unroll 8
        for (int k = 0; k < KST; ++k) s += __expf(salpha[sub][k] - m);
        out[b] = __logf(s) + m + M - score;
    }
}

extern "C" void kernel_launch(void* const* d_in, const int* in_sizes, int n_in,
                              void* d_out, int out_size)
{
    const float* emis  = (const float*)d_in[0];   // output (B,T,K) fp32
    const int*   lab   = (const int*)  d_in[1];   // label_input (B,T) int32
    const float* trans = (const float*)d_in[2];   // transition_params (K,K) fp32
    float*       outp  = (float*)d_out;           // (B,) fp32

    const int B = out_size;                       // 1024
    crf_nll_kernel<<<B / 2, BDIM>>>(emis, lab, trans, outp);
}

// round 3
// speedup vs baseline: 1.2927x; 1.2927x over previous
#include <cuda_runtime.h>
#include <cstdint>

#define KST  48
#define TLEN 512
#define BDIM 96    // 2 batches x 48 states = 3 full warps
#define TILE 8     // time-steps per emission tile (== renorm cadence)

// ---- packed f32x2 helpers (sm_100+) ----
__device__ __forceinline__ unsigned long long fma2(unsigned long long a,
                                                   unsigned long long b,
                                                   unsigned long long c) {
    unsigned long long d;
    asm("fma.rn.f32x2 %0, %1, %2, %3;" : "=l"(d) : "l"(a), "l"(b), "l"(c));
    return d;
}
__device__ __forceinline__ unsigned long long add2(unsigned long long a,
                                                   unsigned long long b) {
    unsigned long long d;
    asm("add.rn.f32x2 %0, %1, %2;" : "=l"(d) : "l"(a), "l"(b));
    return d;
}
__device__ __forceinline__ unsigned long long pack2(float lo, float hi) {
    unsigned long long r;
    asm("mov.b64 %0, {%1, %2};" : "=l"(r) : "f"(lo), "f"(hi));
    return r;
}
__device__ __forceinline__ float2 unpack2(unsigned long long v) {
    float2 f;
    asm("mov.b64 {%0, %1}, %2;" : "=f"(f.x), "=f"(f.y) : "l"(v));
    return f;
}

__global__ __launch_bounds__(BDIM)
void crf_nll_kernel(const float* __restrict__ emis,   // [B, T, K]
                    const int*   __restrict__ lab,    // [B, T]
                    const float* __restrict__ trans,  // [K, K]
                    float*       __restrict__ out)    // [B]
{
    __shared__ __align__(16) float strans[KST * KST];      // raw trans
    __shared__ __align__(16) float etile[2][TILE * KST];   // current tile of emissions, per sub-batch
    __shared__ __align__(16) float pbuf[2][2][KST];        // ping-pong p = exp(alpha)
    __shared__ __align__(16) float salpha[2][KST];         // alpha exchange for renorm
    __shared__ float sred[BDIM];

    const int tid = threadIdx.x;
    const int sub = tid / KST;            // which batch within the block (0/1)
    const int j   = tid - sub * KST;      // output state owned by this thread
    const int b   = blockIdx.x * 2 + sub;

    // stage transition matrix in shared
    for (int i = tid; i < KST * KST; i += BDIM) strans[i] = trans[i];
    __syncthreads();

    // E column in registers, packed as 24 f32x2: ec2[q] = (exp(T[2q][j]), exp(T[2q+1][j]))
    unsigned long long ec2[KST / 2];
#pragma unroll
    for (int q = 0; q < KST / 2; ++q) {
        float e0 = __expf(strans[(2 * q)     * KST + j]);
        float e1 = __expf(strans[(2 * q + 1) * KST + j]);
        ec2[q] = pack2(e0, e1);
    }

    // ---- sequence score (unary + binary), t-strided across 48 threads per batch ----
    const int*   lb  = lab  + b * TLEN;
    const float* eb0 = emis + (size_t)b * TLEN * KST;
    float part = 0.f;
    for (int t = j; t < TLEN; t += KST) {
        int l0 = lb[t];
        part += eb0[t * KST + l0];
        if (t + 1 < TLEN) part += strans[l0 * KST + lb[t + 1]];
    }
    sred[tid] = part;
    __syncthreads();
    float score = 0.f;
    if (j == 0) {
#pragma unroll 8
        for (int k = 0; k < KST; ++k) score += sred[sub * KST + k];
    }

    // ---- forward recursion, tiled emission prefetch ----
    // Tile g covers t in [1+8g, 8+8g]; tile 63 has 7 valid steps (t<=511).
    const float* ebA = emis + (size_t)(blockIdx.x * 2)     * TLEN * KST;
    const float* ebB = emis + (size_t)(blockIdx.x * 2 + 1) * TLEN * KST;

    float a = eb0[j];                     // alpha at t=0 (relative to running base M)
    float M = 0.f;                        // running log-base

    // prologue: fetch tile 0 into registers
    float4 vA, vB;
    {
        int ofs = 1 * KST + 4 * tid;      // t0 = 1
        vA = *(const float4*)(ebA + ofs);
        vB = *(const float4*)(ebB + ofs);
    }

    int par = 0;
    for (int g = 0; g < (TLEN + TILE - 2) / TILE; ++g) {       // 64 tiles
        // renorm exchange (also the tile boundary barrier)
        salpha[sub][j] = a;
        __syncthreads();

        // commit current tile (all old-tile reads completed before the barrier);
        // these STS are drained by the first step's pbuf barrier below.
        ((float4*)&etile[0][0])[tid] = vA;
        ((float4*)&etile[1][0])[tid] = vB;

        // issue next tile's loads: ~1200 cycles of compute to hide ~577-cycle DRAM latency
        if (g + 1 < 64) {
            int ofs = (9 + 8 * g) * KST + 4 * tid;
            int cof = min(ofs, TLEN * KST - 4);   // clamp final partial tile
            vA = *(const float4*)(ebA + cof);
            vB = *(const float4*)(ebB + cof);
        }

        // renormalize every tile (8 steps)
        {
            const float4* ap = (const float4*)&salpha[sub][0];
            float m = -3.4e38f;
#pragma unroll
            for (int q = 0; q < KST / 4; ++q) {
                float4 v = ap[q];
                m = fmaxf(m, fmaxf(fmaxf(v.x, v.y), fmaxf(v.z, v.w)));
            }
            a -= m;
            M += m;
        }

#pragma unroll
        for (int tt = 0; tt < TILE; ++tt) {
            if (8 * g + tt + 1 >= TLEN) break;    // uniform across block

            pbuf[par][sub][j] = __expf(a);
            __syncthreads();

            // emission read early so LDS latency overlaps the dot
            float e = etile[sub][tt * KST + j];

            // s_j = sum_i p[i] * E[i][j]; packed f32x2, 4 independent chains
            const ulonglong2* pp = (const ulonglong2*)&pbuf[par][sub][0];
            unsigned long long a0 = 0ull, a1 = 0ull, a2 = 0ull, a3 = 0ull;
#pragma unroll
            for (int q = 0; q < KST / 4; q += 2) {
                ulonglong2 v0 = pp[q];
                ulonglong2 v1 = pp[q + 1];
                a0 = fma2(v0.x, ec2[2 * q],     a0);
                a1 = fma2(v0.y, ec2[2 * q + 1], a1);
                a2 = fma2(v1.x, ec2[2 * q + 2], a2);
                a3 = fma2(v1.y, ec2[2 * q + 3], a3);
            }
            a0 = add2(a0, a2);
            a1 = add2(a1, a3);
            a0 = add2(a0, a1);
            float2 f = unpack2(a0);
            float s  = f.x + f.y;

            a = __logf(s) + e;
            par ^= 1;
        }
    }

    // ---- final logsumexp + output ----
    salpha[sub][j] = a;
    __syncthreads();
    if (j == 0) {
        float m = -3.4e38f;
#pragma unroll 8
        for (int k = 0; k < KST; ++k) m = fmaxf(m, salpha[sub][k]);
        float s = 0.f;
#pragma unroll 8
        for (int k = 0; k < KST; ++k) s += __expf(salpha[sub][k] - m);
        out[b] = __logf(s) + m + M - score;
    }
}

extern "C" void kernel_launch(void* const* d_in, const int* in_sizes, int n_in,
                              void* d_out, int out_size)
{
    const float* emis  = (const float*)d_in[0];   // output (B,T,K) fp32
    const int*   lab   = (const int*)  d_in[1];   // label_input (B,T) int32
    const float* trans = (const float*)d_in[2];   // transition_params (K,K) fp32
    float*       outp  = (float*)d_out;           // (B,) fp32

    const int B = out_size;                       // 1024
    crf_nll_kernel<<<B / 2, BDIM>>>(emis, lab, trans, outp);
}

// round 4
// speedup vs baseline: 1.6520x; 1.2779x over previous
#include <cuda_runtime.h>
#include <cstdint>

#define KST   48
#define TLEN  512
#define GRP   16              // threads per batch
#define NB    4               // batches per block
#define BDIM  (GRP * NB)      // 64 threads = 2 warps
#define TILE  8               // steps per emission tile (= renorm cadence)
#define NTILE 64
#define ETS   400             // etile per-batch float stride (pad: +16 banks)

// ---- packed f32x2 helpers (sm_100+) ----
__device__ __forceinline__ unsigned long long fma2(unsigned long long a,
                                                   unsigned long long b,
                                                   unsigned long long c) {
    unsigned long long d;
    asm("fma.rn.f32x2 %0, %1, %2, %3;" : "=l"(d) : "l"(a), "l"(b), "l"(c));
    return d;
}
__device__ __forceinline__ unsigned long long add2(unsigned long long a,
                                                   unsigned long long b) {
    unsigned long long d;
    asm("add.rn.f32x2 %0, %1, %2;" : "=l"(d) : "l"(a), "l"(b));
    return d;
}
__device__ __forceinline__ unsigned long long pack2(float lo, float hi) {
    unsigned long long r;
    asm("mov.b64 %0, {%1, %2};" : "=l"(r) : "f"(lo), "f"(hi));
    return r;
}
__device__ __forceinline__ float2 unpack2(unsigned long long v) {
    float2 f;
    asm("mov.b64 {%0, %1}, %2;" : "=f"(f.x), "=f"(f.y) : "l"(v));
    return f;
}
__device__ __forceinline__ float ex2f(float x) {
    float y; asm("ex2.approx.f32 %0, %1;" : "=f"(y) : "f"(x)); return y;
}
__device__ __forceinline__ float lg2f(float x) {
    float y; asm("lg2.approx.f32 %0, %1;" : "=f"(y) : "f"(x)); return y;
}

__global__ __launch_bounds__(BDIM)
void crf_nll_kernel(const float* __restrict__ emis,   // [B, T, K]
                    const int*   __restrict__ lab,    // [B, T]
                    const float* __restrict__ trans,  // [K, K]
                    float*       __restrict__ out)    // [B]
{
    __shared__ __align__(16) float strans[KST * KST];
    __shared__ __align__(16) float etile[NB * ETS];      // per-batch emission tile (log2-scaled)
    __shared__ __align__(16) float pbuf[2][NB][KST];     // ping-pong p = 2^alpha

    const int tid = threadIdx.x;
    const int g   = tid >> 4;          // batch within block (0..3)
    const int l   = tid & 15;          // lane within batch group
    const int b   = blockIdx.x * NB + g;
    const float LOG2E = 1.4426950408889634f;
    const float LN2   = 0.6931471805599453f;

    // stage transition matrix
    for (int i = tid; i < KST * KST; i += BDIM) strans[i] = trans[i];
    __syncthreads();

    // E columns for states j = l, l+16, l+32; packed pairs (linear domain)
    unsigned long long ec2[3][KST / 2];
#pragma unroll
    for (int s = 0; s < 3; ++s) {
        const int col = l + 16 * s;
#pragma unroll
        for (int q = 0; q < KST / 2; ++q) {
            float e0 = __expf(strans[(2 * q)     * KST + col]);
            float e1 = __expf(strans[(2 * q + 1) * KST + col]);
            ec2[s][q] = pack2(e0, e1);
        }
    }

    // ---- sequence score (unary + binary), strided across 16 threads per batch ----
    const int*   lb = lab + b * TLEN;
    const float* eb = emis + (size_t)b * TLEN * KST;
    float part = 0.f;
    for (int t = l; t < TLEN; t += GRP) {
        int l0 = lb[t];
        part += eb[t * KST + l0];
        if (t + 1 < TLEN) part += strans[l0 * KST + lb[t + 1]];
    }
#pragma unroll
    for (int d = 8; d >= 1; d >>= 1)
        part += __shfl_xor_sync(0xffffffffu, part, d, 16);
    const float score = part;

    // ---- forward recursion in log2 domain ----
    float a0 = eb[l]      * LOG2E;
    float a1 = eb[l + 16] * LOG2E;
    float a2 = eb[l + 32] * LOG2E;
    float M  = 0.f;                      // running log2-base

    // prefetch tile 0 (t = 1..8) into registers
    const float4* src4 = (const float4*)eb;
    const int     maxf4 = (TLEN * KST) / 4 - 1;
    float4 r[6];
#pragma unroll
    for (int k = 0; k < 6; ++k)
        r[k] = src4[(1 * KST) / 4 + l + 16 * k];

    float* myTile = etile + g * ETS;
    float* pb0 = &pbuf[0][g][0];
    float* pb1 = &pbuf[1][g][0];
    int par = 0;

    for (int gt = 0; gt < NTILE; ++gt) {
        // renormalize (max over the batch's 48 alphas)
        float m = fmaxf(a0, fmaxf(a1, a2));
#pragma unroll
        for (int d = 8; d >= 1; d >>= 1)
            m = fmaxf(m, __shfl_xor_sync(0xffffffffu, m, d, 16));
        a0 -= m; a1 -= m; a2 -= m; M += m;

        // commit current tile to shared (scaled to log2 units)
#pragma unroll
        for (int k = 0; k < 6; ++k) {
            float4 v = r[k];
            v.x *= LOG2E; v.y *= LOG2E; v.z *= LOG2E; v.w *= LOG2E;
            ((float4*)myTile)[l + 16 * k] = v;
        }

        // prefetch next tile (clamped; clamped rows are never consumed)
        if (gt + 1 < NTILE) {
            const int base = ((1 + TILE * (gt + 1)) * KST) / 4;
#pragma unroll
            for (int k = 0; k < 6; ++k)
                r[k] = src4[min(base + l + 16 * k, maxf4)];
        }

        __syncwarp();   // orders etile STS before this tile's reads

#pragma unroll
        for (int tt = 0; tt < TILE; ++tt) {
            const int t = 1 + TILE * gt + tt;
            if (t >= TLEN) break;                     // uniform across block

            float p0 = ex2f(a0), p1 = ex2f(a1), p2 = ex2f(a2);
            float* pb = par ? pb1 : pb0;
            pb[l] = p0; pb[l + 16] = p1; pb[l + 32] = p2;
            __syncwarp();

            // emissions early (overlap LDS latency with the dot)
            float e0 = myTile[tt * KST + l];
            float e1 = myTile[tt * KST + l + 16];
            float e2 = myTile[tt * KST + l + 32];

            // 3 dots over the shared p-vector; 2 chains per output
            const ulonglong2* pp = (const ulonglong2*)pb;
            unsigned long long c00 = 0, c01 = 0, c10 = 0, c11 = 0, c20 = 0, c21 = 0;
#pragma unroll
            for (int q = 0; q < KST / 4; ++q) {       // 12 x LDS.128
                ulonglong2 v = pp[q];
                c00 = fma2(v.x, ec2[0][2 * q],     c00);
                c01 = fma2(v.y, ec2[0][2 * q + 1], c01);
                c10 = fma2(v.x, ec2[1][2 * q],     c10);
                c11 = fma2(v.y, ec2[1][2 * q + 1], c11);
                c20 = fma2(v.x, ec2[2][2 * q],     c20);
                c21 = fma2(v.y, ec2[2][2 * q + 1], c21);
            }
            c00 = add2(c00, c01);
            c10 = add2(c10, c11);
            c20 = add2(c20, c21);
            float2 f0 = unpack2(c00), f1 = unpack2(c10), f2 = unpack2(c20);

            a0 = lg2f(f0.x + f0.y) + e0;
            a1 = lg2f(f1.x + f1.y) + e1;
            a2 = lg2f(f2.x + f2.y) + e2;
            par ^= 1;
        }
    }

    // ---- final logsumexp (log2 domain) + output ----
    float m = fmaxf(a0, fmaxf(a1, a2));
#pragma unroll
    for (int d = 8; d >= 1; d >>= 1)
        m = fmaxf(m, __shfl_xor_sync(0xffffffffu, m, d, 16));
    float ssum = ex2f(a0 - m) + ex2f(a1 - m) + ex2f(a2 - m);
#pragma unroll
    for (int d = 8; d >= 1; d >>= 1)
        ssum += __shfl_xor_sync(0xffffffffu, ssum, d, 16);

    if (l == 0)
        out[b] = LN2 * (lg2f(ssum) + m + M) - score;
}

extern "C" void kernel_launch(void* const* d_in, const int* in_sizes, int n_in,
                              void* d_out, int out_size)
{
    const float* emis  = (const float*)d_in[0];   // output (B,T,K) fp32
    const int*   lab   = (const int*)  d_in[1];   // label_input (B,T) int32
    const float* trans = (const float*)d_in[2];   // transition_params (K,K) fp32
    float*       outp  = (float*)d_out;           // (B,) fp32

    const int B = out_size;                       // 1024
    crf_nll_kernel<<<B / NB, BDIM>>>(emis, lab, trans, outp);
}